// round 2
// baseline (speedup 1.0000x reference)
#include <cuda_runtime.h>

#define SEQ   1024
#define HID   512
#define GATES 2048
#define EMB   512
#define G_CTAS 64
#define UNITS_PER 8   // HID / G_CTAS

// ---------------- device scratch (static, no allocation) ----------------
__device__ float g_xg[SEQ * GATES];   // 8 MB precomputed input gates (fits in L2)
__device__ float g_h[2][HID];         // double-buffered hidden state
__device__ unsigned g_bar;            // grid barrier counter

__device__ __forceinline__ float sigmf(float x) {
    return 1.0f / (1.0f + expf(-x));
}

// ---------------- init: reset barrier + zero h (runs every replay) ------
__global__ void init_kernel() {
    int t = blockIdx.x * blockDim.x + threadIdx.x;
    if (t == 0) g_bar = 0u;
    if (t < 2 * HID) ((float*)g_h)[t] = 0.0f;
}

// ---------------- kernel 1: x_gates = emb[tok] @ w_ih^T + (b_ih+b_hh) ---
// BM=64 tokens, BN=64 gates, BK=32, 256 threads, 4x4 microtile per thread.
__global__ void __launch_bounds__(256) xgates_gemm(
    const int*   __restrict__ tok,
    const float* __restrict__ emb,
    const float* __restrict__ w_ih,
    const float* __restrict__ b_ih,
    const float* __restrict__ b_hh)
{
    __shared__ float As[32][68];   // [k][token-row], pad 68 keeps float4 align + no store conflicts
    __shared__ float Bs[32][68];   // [k][gate-row]
    __shared__ int   stok[64];

    const int tid = threadIdx.x;
    const int bm = blockIdx.y * 64;   // token base
    const int bn = blockIdx.x * 64;   // gate base

    if (tid < 64) stok[tid] = tok[bm + tid];
    __syncthreads();

    float acc[4][4];
    #pragma unroll
    for (int i = 0; i < 4; i++)
        #pragma unroll
        for (int j = 0; j < 4; j++) acc[i][j] = 0.0f;

    const int tr = tid >> 4;    // 0..15 -> token sub-rows
    const int tc = tid & 15;    // 0..15 -> gate sub-cols

    for (int k0 = 0; k0 < EMB; k0 += 32) {
        #pragma unroll
        for (int i = 0; i < 2; i++) {
            int idx = tid + 256 * i;        // 0..511
            int row = idx & 63;             // warp-contiguous rows -> conflict-free STS
            int k4  = idx >> 6;             // 0..7
            float4 av = *reinterpret_cast<const float4*>(
                emb + (size_t)stok[row] * EMB + k0 + k4 * 4);
            As[k4*4+0][row] = av.x; As[k4*4+1][row] = av.y;
            As[k4*4+2][row] = av.z; As[k4*4+3][row] = av.w;
            float4 bv = *reinterpret_cast<const float4*>(
                w_ih + (size_t)(bn + row) * EMB + k0 + k4 * 4);
            Bs[k4*4+0][row] = bv.x; Bs[k4*4+1][row] = bv.y;
            Bs[k4*4+2][row] = bv.z; Bs[k4*4+3][row] = bv.w;
        }
        __syncthreads();

        #pragma unroll
        for (int kk = 0; kk < 32; kk++) {
            float4 a4 = *reinterpret_cast<const float4*>(&As[kk][tr * 4]);
            float4 b4 = *reinterpret_cast<const float4*>(&Bs[kk][tc * 4]);
            float a[4] = {a4.x, a4.y, a4.z, a4.w};
            float b[4] = {b4.x, b4.y, b4.z, b4.w};
            #pragma unroll
            for (int i = 0; i < 4; i++)
                #pragma unroll
                for (int j = 0; j < 4; j++)
                    acc[i][j] = fmaf(a[i], b[j], acc[i][j]);
        }
        __syncthreads();
    }

    const int gcol = bn + tc * 4;
    float4 bias;
    bias.x = b_ih[gcol + 0] + b_hh[gcol + 0];
    bias.y = b_ih[gcol + 1] + b_hh[gcol + 1];
    bias.z = b_ih[gcol + 2] + b_hh[gcol + 2];
    bias.w = b_ih[gcol + 3] + b_hh[gcol + 3];
    #pragma unroll
    for (int i = 0; i < 4; i++) {
        int trow = bm + tr * 4 + i;
        float4 v;
        v.x = acc[i][0] + bias.x;
        v.y = acc[i][1] + bias.y;
        v.z = acc[i][2] + bias.z;
        v.w = acc[i][3] + bias.w;
        *reinterpret_cast<float4*>(g_xg + (size_t)trow * GATES + gcol) = v;
    }
}

// ---------------- kernel 2: persistent LSTM scan -------------------------
// 64 CTAs x 256 threads. CTA owns 8 hidden units (32 gate rows).
// Each warp: 4 rows; each lane: 16-element k-slice held in registers.
__global__ void __launch_bounds__(256, 1) lstm_scan(const float* __restrict__ w_hh)
{
    const int tid  = threadIdx.x;
    const int warp = tid >> 5;
    const int lane = tid & 31;
    const int base = blockIdx.x * UNITS_PER;

    // Preload weight slices into registers (persistent across all 1024 steps).
    float w[4][16];
    #pragma unroll
    for (int q = 0; q < 4; q++) {
        int lr   = warp * 4 + q;                       // local row 0..31
        int grow = (lr >> 3) * HID + base + (lr & 7);  // gate*512 + base + unit
        const float4* src =
            reinterpret_cast<const float4*>(w_hh + (size_t)grow * HID) + lane * 4;
        float4 v0 = src[0], v1 = src[1], v2 = src[2], v3 = src[3];
        w[q][0]=v0.x; w[q][1]=v0.y; w[q][2]=v0.z; w[q][3]=v0.w;
        w[q][4]=v1.x; w[q][5]=v1.y; w[q][6]=v1.z; w[q][7]=v1.w;
        w[q][8]=v2.x; w[q][9]=v2.y; w[q][10]=v2.z; w[q][11]=v2.w;
        w[q][12]=v3.x; w[q][13]=v3.y; w[q][14]=v3.z; w[q][15]=v3.w;
    }

    __shared__ float gates_s[32];
    float c_state = 0.0f;

    for (int t = 0; t < SEQ; t++) {
        // h_{t-1} lives in buffer (t-1)&1 == (t+1)&1 ; zeros for t==0 (init kernel).
        // __ldcg: L2-only read — L1 is stale across SMs within this launch.
        const float4* hsrc =
            reinterpret_cast<const float4*>(g_h[(t + 1) & 1]) + lane * 4;
        float4 h0 = __ldcg(hsrc + 0);
        float4 h1 = __ldcg(hsrc + 1);
        float4 h2 = __ldcg(hsrc + 2);
        float4 h3 = __ldcg(hsrc + 3);

        // Issue xg loads early (latency hidden behind FMA chain). L2-resident.
        float xgv0 = 0.f, xgv1 = 0.f, xgv2 = 0.f, xgv3 = 0.f;
        if (tid < 8) {
            const float* xp = g_xg + (size_t)t * GATES + base + tid;
            xgv0 = __ldg(xp);
            xgv1 = __ldg(xp + 512);
            xgv2 = __ldg(xp + 1024);
            xgv3 = __ldg(xp + 1536);
        }

        float hv[16] = {h0.x,h0.y,h0.z,h0.w, h1.x,h1.y,h1.z,h1.w,
                        h2.x,h2.y,h2.z,h2.w, h3.x,h3.y,h3.z,h3.w};

        float acc0 = 0.f, acc1 = 0.f, acc2 = 0.f, acc3 = 0.f;
        #pragma unroll
        for (int m = 0; m < 16; m++) {
            float h = hv[m];
            acc0 = fmaf(w[0][m], h, acc0);
            acc1 = fmaf(w[1][m], h, acc1);
            acc2 = fmaf(w[2][m], h, acc2);
            acc3 = fmaf(w[3][m], h, acc3);
        }
        #pragma unroll
        for (int off = 16; off; off >>= 1) {
            acc0 += __shfl_xor_sync(0xffffffffu, acc0, off);
            acc1 += __shfl_xor_sync(0xffffffffu, acc1, off);
            acc2 += __shfl_xor_sync(0xffffffffu, acc2, off);
            acc3 += __shfl_xor_sync(0xffffffffu, acc3, off);
        }
        if (lane == 0) {
            gates_s[warp * 4 + 0] = acc0;
            gates_s[warp * 4 + 1] = acc1;
            gates_s[warp * 4 + 2] = acc2;
            gates_s[warp * 4 + 3] = acc3;
        }
        __syncthreads();

        if (tid < 8) {
            float gi = sigmf(gates_s[tid]      + xgv0);
            float gf = sigmf(gates_s[8 + tid]  + xgv1);
            float gg = tanhf(gates_s[16 + tid] + xgv2);
            float go = sigmf(gates_s[24 + tid] + xgv3);
            c_state = gf * c_state + gi * gg;
            float hn = go * tanhf(c_state);
            __stcg(&g_h[t & 1][base + tid], hn);
            __threadfence();   // publish h before arriving (each writer fences)
        }
        __syncthreads();

        if (tid == 0) {
            atomicAdd(&g_bar, 1u);
            unsigned target = (unsigned)(t + 1) * G_CTAS;
            while (*((volatile unsigned*)&g_bar) < target) { }
            __threadfence();   // acquire: order subsequent h loads after observation
        }
        __syncthreads();
    }
}

// ---------------- kernel 3: attention head + outputs ---------------------
__global__ void __launch_bounds__(256) finalize_kernel(
    const float* __restrict__ attn_w,
    const float* __restrict__ attn_b,
    float* __restrict__ out)
{
    __shared__ float red[8];
    const int o   = blockIdx.x;      // 0..63
    const int tid = threadIdx.x;
    const float* h = g_h[1];         // h after t=1023 (1023&1 == 1)

    float s = 0.f;
    for (int k = tid; k < HID; k += 256)
        s = fmaf(h[k], attn_w[o * HID + k], s);
    #pragma unroll
    for (int off = 16; off; off >>= 1)
        s += __shfl_xor_sync(0xffffffffu, s, off);
    if ((tid & 31) == 0) red[tid >> 5] = s;
    __syncthreads();
    if (tid == 0) {
        float tot = 0.f;
        #pragma unroll
        for (int i = 0; i < 8; i++) tot += red[i];
        red[0] = sigmf(tot + attn_b[o]);
    }
    __syncthreads();
    float a = red[0];
    // x_attention: (1, 64, 32, 32) broadcast
    for (int p = tid; p < 1024; p += 256)
        out[o * 1024 + p] = a;
    // x_instr_rep: (1, 512) after the attention tensor
    if (o == 0)
        for (int j = tid; j < HID; j += 256)
            out[65536 + j] = h[j];
}

// ---------------- launch -------------------------------------------------
extern "C" void kernel_launch(void* const* d_in, const int* in_sizes, int n_in,
                              void* d_out, int out_size)
{
    const int*   tok    = (const int*)  d_in[0];
    const float* emb    = (const float*)d_in[1];
    const float* w_ih   = (const float*)d_in[2];
    const float* w_hh   = (const float*)d_in[3];
    const float* b_ih   = (const float*)d_in[4];
    const float* b_hh   = (const float*)d_in[5];
    const float* attn_w = (const float*)d_in[6];
    const float* attn_b = (const float*)d_in[7];
    float* out = (float*)d_out;

    init_kernel<<<4, 256>>>();
    dim3 gg(GATES / 64, SEQ / 64);           // 32 x 16 blocks
    xgates_gemm<<<gg, 256>>>(tok, emb, w_ih, b_ih, b_hh);
    lstm_scan<<<G_CTAS, 256>>>(w_hh);
    finalize_kernel<<<64, 256>>>(attn_w, attn_b, out);
}